// round 15
// baseline (speedup 1.0000x reference)
#include <cuda_runtime.h>
#include <cuda_bf16.h>
#include <math.h>
#include <stdint.h>

#define BB 16
#define TT_ 81
#define DD 128
#define HH 8
#define BT (BB*TT_)       // 1296

__device__ float g_bo[BB*HH*TT_*DD];
__device__ float g_G[BT*DD];

// ---------------- packed fp32x2 helpers ----------------
static __device__ __forceinline__ unsigned long long add2(unsigned long long a,
                                                          unsigned long long b) {
    unsigned long long r;
    asm("add.rn.f32x2 %0, %1, %2;" : "=l"(r) : "l"(a), "l"(b));
    return r;
}
static __device__ __forceinline__ float2 unpack2(unsigned long long v) {
    float2 f;
    asm("mov.b64 {%0, %1}, %2;" : "=f"(f.x), "=f"(f.y) : "l"(v));
    return f;
}
#define ABS2MASK 0x7FFFFFFF7FFFFFFFULL

static __device__ __forceinline__ uint32_t smem_to_u32(const void* p) {
    uint32_t a;
    asm("{ .reg .u64 t; cvta.to.shared.u64 t, %1; cvt.u32.u64 %0, t; }" : "=r"(a) : "l"(p));
    return a;
}
#define LDMX4(r0, r1, r2, r3, addr) \
    asm volatile("ldmatrix.sync.aligned.m8n8.x4.shared.b16 {%0,%1,%2,%3}, [%4];" \
        : "=r"(r0), "=r"(r1), "=r"(r2), "=r"(r3) : "r"(addr))
#define MMA16816(c, a0, a1, a2, a3, b0, b1) \
    asm volatile("mma.sync.aligned.m16n8k16.row.col.f32.bf16.bf16.f32 " \
        "{%0,%1,%2,%3}, {%4,%5,%6,%7}, {%8,%9}, {%0,%1,%2,%3};" \
        : "+f"((c)[0]), "+f"((c)[1]), "+f"((c)[2]), "+f"((c)[3]) \
        : "r"(a0), "r"(a1), "r"(a2), "r"(a3), "r"(b0), "r"(b1))

// split 8 floats -> bf16-hi uint4 + bf16-lo uint4
static __device__ __forceinline__ void split8(float4 a, float4 b, uint4& hi, uint4& lo) {
    float va[8] = {a.x, a.y, a.z, a.w, b.x, b.y, b.z, b.w};
    unsigned short h[8], l[8];
#pragma unroll
    for (int i = 0; i < 8; i++) {
        __nv_bfloat16 bh = __float2bfloat16(va[i]);
        h[i] = __bfloat16_as_ushort(bh);
        l[i] = __bfloat16_as_ushort(__float2bfloat16(va[i] - __bfloat162float(bh)));
    }
    hi = make_uint4((uint32_t)h[0]|((uint32_t)h[1]<<16), (uint32_t)h[2]|((uint32_t)h[3]<<16),
                    (uint32_t)h[4]|((uint32_t)h[5]<<16), (uint32_t)h[6]|((uint32_t)h[7]<<16));
    lo = make_uint4((uint32_t)l[0]|((uint32_t)l[1]<<16), (uint32_t)l[2]|((uint32_t)l[3]<<16),
                    (uint32_t)l[4]|((uint32_t)l[5]<<16), (uint32_t)l[6]|((uint32_t)l[7]<<16));
}
// cvt-only: 8 floats -> bf16-hi uint4
static __device__ __forceinline__ uint4 cvt8(float4 a, float4 b) {
    float va[8] = {a.x, a.y, a.z, a.w, b.x, b.y, b.z, b.w};
    unsigned short h[8];
#pragma unroll
    for (int i = 0; i < 8; i++) h[i] = __bfloat16_as_ushort(__float2bfloat16(va[i]));
    return make_uint4((uint32_t)h[0]|((uint32_t)h[1]<<16), (uint32_t)h[2]|((uint32_t)h[3]<<16),
                      (uint32_t)h[4]|((uint32_t)h[5]<<16), (uint32_t)h[6]|((uint32_t)h[7]<<16));
}

// ---- smem layout (identical to R14) ----
#define AHI_B   0
#define ALO_B   26112
#define WB_B    52224
#define SBHI_B  0
#define SBLO_B  19968
#define VTHI_B  52224
#define VTLO_B  78848
#define KT_F    30464
#define LDS_S   84
#define S_F     41216
#define MSK_F   48020
#define BIAS_F  54584
#define SMEM_FLOATS (BIAS_F + 256)   // 54840 fl = 219360 B
#define QV_LD   132
#define SB_LD   208

#define NT_ 1024

__global__ void __launch_bounds__(NT_, 1)
attn_mma(const float* __restrict__ x,
         const float* __restrict__ wqkv_w,
         const float* __restrict__ wqkv_b,
         const float* __restrict__ wk_w,
         const float* __restrict__ msk,
         const float* __restrict__ head_en,
         float* __restrict__ ap_out) {
    extern __shared__ float sm[];
    char* smb = (char*)sm;
    const uint32_t sb = smem_to_u32(sm);
    float* Qs  = sm;                 // stride 132, overlays A after GEMM
    float* KT  = sm + KT_F;
    float* S   = sm + S_F;
    float* Msk = sm + MSK_F;
    float* BiasS = sm + BIAS_F;

    const int b = blockIdx.x >> 3;
    const int h = blockIdx.x & 7;
    const int tid = threadIdx.x;
    const int wid = tid >> 5;
    const int lane = tid & 31;

    const float* xb = x + (size_t)b * TT_ * DD;
    const float* Wg = wqkv_w + ((size_t)h * 2 * DD) * DD;   // 256 x 128

    // ---------------- S1: stage A hi/lo, W hi, bias, KT, Msk ----------------
    for (int idx = tid; idx < 96 * 16; idx += NT_) {        // A: (t, k8)
        int t = idx >> 4, k0 = (idx & 15) << 3;
        uint4 hi = make_uint4(0, 0, 0, 0), lo = make_uint4(0, 0, 0, 0);
        if (t < TT_) {
            float4 va = *(const float4*)(xb + t * DD + k0);
            float4 vb = *(const float4*)(xb + t * DD + k0 + 4);
            split8(va, vb, hi, lo);
        }
        uint32_t off = (uint32_t)t * 272 + (uint32_t)k0 * 2;
        *(uint4*)(smb + AHI_B + off) = hi;
        *(uint4*)(smb + ALO_B + off) = lo;
    }
    for (int idx = tid; idx < 256 * 16; idx += NT_) {       // W hi only: (n, k8)
        int n = idx >> 4, k0 = (idx & 15) << 3;
        float4 va = *(const float4*)(Wg + (size_t)n * DD + k0);
        float4 vb = *(const float4*)(Wg + (size_t)n * DD + k0 + 4);
        *(uint4*)(smb + WB_B + (uint32_t)n * 272 + (uint32_t)k0 * 2) = cvt8(va, vb);
    }
    if (tid < 256) BiasS[tid] = wqkv_b[h * 256 + tid];
    {   // KT (negated k), Msk
        const float4* x4  = (const float4*)xb;
        const float4* wk4 = (const float4*)(wk_w + h * DD);
        for (int i = tid; i < 32 * TT_; i += NT_) {
            int dq = i / TT_, t = i - dq * TT_;
            float4 xv = x4[t * 32 + dq];
            float4 wv = wk4[dq];
            int dp = dq * 2;
            *(float2*)&KT[(dp    ) * 168 + t * 2] = make_float2(-(xv.x*wv.x), -(xv.y*wv.y));
            *(float2*)&KT[(dp + 1) * 168 + t * 2] = make_float2(-(xv.z*wv.z), -(xv.w*wv.w));
        }
        for (int i = tid; i < 192; i += NT_) {
            int dp = i / 3, s = 81 + (i % 3);
            *(float2*)&KT[dp * 168 + s * 2] = make_float2(0.f, 0.f);
        }
        const float* mg = msk + (size_t)h * TT_ * TT_;
        for (int i = tid; i < TT_ * TT_; i += NT_) Msk[i] = mg[i];
    }
    __syncthreads();

    // ---------------- QKV GEMM: 32 warps x (3 m16 x 2 n8), 2 passes ----------------
    const int j = lane >> 3, lr = lane & 7;
    {
        const int mgrp = wid >> 4, ngrp = wid & 15;
        const int mb = mgrp * 48, nb = ngrp * 16;
        const uint32_t aOff = (uint32_t)(mb + ((j & 1) << 3) + lr) * 272 + ((uint32_t)(j >> 1) << 4);
        const uint32_t bOff = (uint32_t)(nb + ((j >> 1) << 3) + lr) * 272 + ((uint32_t)(j & 1) << 4);
        const uint32_t aHi = sb + AHI_B + aOff;
        const uint32_t aLo = sb + ALO_B + aOff;
        const uint32_t bBs = sb + WB_B + bOff;

        float acc[3][2][4];
#pragma unroll
        for (int m = 0; m < 3; m++)
#pragma unroll
            for (int n = 0; n < 2; n++)
#pragma unroll
                for (int q = 0; q < 4; q++) acc[m][n][q] = 0.f;

#pragma unroll
        for (int pass = 0; pass < 2; pass++) {
            const uint32_t aB = (pass == 1) ? aLo : aHi;
#pragma unroll
            for (int ks = 0; ks < 8; ks++) {
                const uint32_t ko = (uint32_t)ks * 32;
                uint32_t ar[3][4], br[4];
#pragma unroll
                for (int mt = 0; mt < 3; mt++)
                    LDMX4(ar[mt][0], ar[mt][1], ar[mt][2], ar[mt][3],
                          aB + (uint32_t)mt * (16 * 272) + ko);
                LDMX4(br[0], br[1], br[2], br[3], bBs + ko);
#pragma unroll
                for (int mt = 0; mt < 3; mt++)
#pragma unroll
                    for (int ns = 0; ns < 2; ns++)
                        MMA16816(acc[mt][ns], ar[mt][0], ar[mt][1], ar[mt][2], ar[mt][3],
                                 br[ns * 2], br[ns * 2 + 1]);
            }
        }
        __syncthreads();    // all ldmatrix reads done before overlays

        // epilogue: +bias; n<128 -> Qs fp32; n>=128 -> VThi/VTlo bf16 [d][s]
        const float he = head_en[h];
        const int r0 = (lane >> 2);
        const int cc = 2 * (lane & 3);
#pragma unroll
        for (int mt = 0; mt < 3; mt++) {
            int rows[2] = { mb + mt * 16 + r0, mb + mt * 16 + r0 + 8 };
#pragma unroll
            for (int ns = 0; ns < 2; ns++) {
                int n = nb + ns * 8 + cc;
                float b0 = BiasS[n], b1 = BiasS[n + 1];
#pragma unroll
                for (int half = 0; half < 2; half++) {
                    int t = rows[half];
                    if (t >= TT_) continue;
                    float v0 = acc[mt][ns][half * 2]     + b0;
                    float v1 = acc[mt][ns][half * 2 + 1] + b1;
                    if (n < 128) {
                        *(float2*)&Qs[t * QV_LD + n] = make_float2(v0, v1);
                    } else {
                        int col = n - 128;
                        float w0 = v0 * he, w1 = v1 * he;
                        __nv_bfloat16 h0 = __float2bfloat16(w0);
                        __nv_bfloat16 h1 = __float2bfloat16(w1);
                        *(__nv_bfloat16*)(smb + VTHI_B + (uint32_t)col * SB_LD + t * 2) = h0;
                        *(__nv_bfloat16*)(smb + VTHI_B + (uint32_t)(col + 1) * SB_LD + t * 2) = h1;
                        *(__nv_bfloat16*)(smb + VTLO_B + (uint32_t)col * SB_LD + t * 2) =
                            __float2bfloat16(w0 - __bfloat162float(h0));
                        *(__nv_bfloat16*)(smb + VTLO_B + (uint32_t)(col + 1) * SB_LD + t * 2) =
                            __float2bfloat16(w1 - __bfloat162float(h1));
                    }
                }
            }
        }
        // zero VT pad cols s=81..95 for all 128 d, both mats
        for (int i = tid; i < 1920; i += NT_) {
            int d = i / 15, s = 81 + (i % 15);
            *(__nv_bfloat16*)(smb + VTHI_B + (uint32_t)d * SB_LD + s * 2) = __float2bfloat16(0.f);
            *(__nv_bfloat16*)(smb + VTLO_B + (uint32_t)d * SB_LD + s * 2) = __float2bfloat16(0.f);
        }
    }
    __syncthreads();

    // ---------------- P2: scores, 861 jobs of 4t x 2s (R7-proven formula) ----------
    const float scale = 0.08838834764831843f;
    if (tid < 861) {
        const int t0s = (tid / 41) * 4;
        const int s0 = (tid % 41) * 2;
        int ti[4];
#pragma unroll
        for (int i = 0; i < 4; i++) ti[i] = min(t0s + i, TT_ - 1);
        unsigned long long sacc[4][2];
#pragma unroll
        for (int i = 0; i < 4; i++) { sacc[i][0] = 0ULL; sacc[i][1] = 0ULL; }
#pragma unroll 1
        for (int d = 0; d < DD; d += 4) {
            const int dp = d >> 1;
            ulonglong2 q[4];
#pragma unroll
            for (int i = 0; i < 4; i++)
                q[i] = *(const ulonglong2*)&Qs[ti[i] * QV_LD + d];
            ulonglong2 ka = *(const ulonglong2*)&KT[(dp    ) * 168 + s0 * 2];
            ulonglong2 kc = *(const ulonglong2*)&KT[(dp + 1) * 168 + s0 * 2];
#pragma unroll
            for (int i = 0; i < 4; i++) {
                unsigned long long u;
                u = add2(q[i].x, ka.x) & ABS2MASK;  sacc[i][0] = add2(sacc[i][0], u);
                u = add2(q[i].y, kc.x) & ABS2MASK;  sacc[i][0] = add2(sacc[i][0], u);
                u = add2(q[i].x, ka.y) & ABS2MASK;  sacc[i][1] = add2(sacc[i][1], u);
                u = add2(q[i].y, kc.y) & ABS2MASK;  sacc[i][1] = add2(sacc[i][1], u);
            }
        }
#pragma unroll
        for (int i = 0; i < 4; i++) {
            if (t0s + i >= TT_) continue;
#pragma unroll
            for (int q = 0; q < 2; q++) {
                if (s0 + q >= TT_) continue;
                float2 f = unpack2(sacc[i][q]);
                S[(s0 + q) * LDS_S + (t0s + i)] = -(f.x + f.y) * scale;
            }
        }
    }
    __syncthreads();

    // ---------------- P3: softmax; writes Sbhi/Sblo [t][s] bf16 + ap ----------------
    if (tid < 352) {
        const int t  = tid >> 2;
        const int l4 = tid & 3;
        const bool valid = (t < TT_);
        const int sBeg = l4 * 21;
        const int sEnd = valid ? min(sBeg + 21, TT_) : sBeg;
        float mx = -1e30f;
        for (int s = sBeg; s < sEnd; s++) mx = fmaxf(mx, S[s * LDS_S + t]);
        mx = fmaxf(mx, __shfl_xor_sync(0xFFFFFFFFu, mx, 1));
        mx = fmaxf(mx, __shfl_xor_sync(0xFFFFFFFFu, mx, 2));
        float sum = 0.f;
        for (int s = sBeg; s < sEnd; s++) {
            float e = __expf(S[s * LDS_S + t] - mx);
            sum += e;
            S[s * LDS_S + t] = e;
        }
        sum += __shfl_xor_sync(0xFFFFFFFFu, sum, 1);
        sum += __shfl_xor_sync(0xFFFFFFFFu, sum, 2);
        float inv = 1.f / sum;
        for (int s = sBeg; s < sEnd; s++) {
            float mval = Msk[t * TT_ + s];
            float a = S[s * LDS_S + t] * inv * mval;
            __nv_bfloat16 hv = __float2bfloat16(a);
            *(__nv_bfloat16*)(smb + SBHI_B + (uint32_t)t * SB_LD + s * 2) = hv;
            *(__nv_bfloat16*)(smb + SBLO_B + (uint32_t)t * SB_LD + s * 2) =
                __float2bfloat16(a - __bfloat162float(hv));
            if (b == 0)
                ap_out[((size_t)t * TT_ + s) * HH + h] = a - 1.f + mval;
        }
    } else if (tid < 512) {
        // zero Sb pads: t rows 81..95 full; s cols 81..95 for t<=80 (both mats)
        for (int i = tid - 352; i < 780; i += 160) {
            int row = 81 + i / 52, w = i % 52;
            *(uint32_t*)(smb + SBHI_B + (uint32_t)row * SB_LD + w * 4) = 0u;
            *(uint32_t*)(smb + SBLO_B + (uint32_t)row * SB_LD + w * 4) = 0u;
        }
        for (int i = tid - 352; i < 1215; i += 160) {
            int t = i / 15, s = 81 + (i % 15);
            *(__nv_bfloat16*)(smb + SBHI_B + (uint32_t)t * SB_LD + s * 2) = __float2bfloat16(0.f);
            *(__nv_bfloat16*)(smb + SBLO_B + (uint32_t)t * SB_LD + s * 2) = __float2bfloat16(0.f);
        }
    }
    __syncthreads();

    // ---------------- P4: AV via HMMA (warps 0-15), 3 passes -> g_bo ----------------
    if (wid < 16) {
        const int mb2 = (wid >> 3) * 48;
        const int nb2 = (wid & 7) * 16;
        const uint32_t aOffAV = (uint32_t)(mb2 + ((j & 1) << 3) + lr) * SB_LD + ((uint32_t)(j >> 1) << 4);
        const uint32_t bOffAV = (uint32_t)(nb2 + ((j >> 1) << 3) + lr) * SB_LD + ((uint32_t)(j & 1) << 4);

        float av[3][2][4];
#pragma unroll
        for (int m = 0; m < 3; m++)
#pragma unroll
            for (int n = 0; n < 2; n++)
#pragma unroll
                for (int q = 0; q < 4; q++) av[m][n][q] = 0.f;

#pragma unroll
        for (int pass = 0; pass < 3; pass++) {
            const uint32_t aB = sb + ((pass == 1) ? SBLO_B : SBHI_B) + aOffAV;
            const uint32_t bB = sb + ((pass == 2) ? VTLO_B : VTHI_B) + bOffAV;
#pragma unroll
            for (int ks = 0; ks < 6; ks++) {
                const uint32_t ko = (uint32_t)ks * 32;
                uint32_t ar[3][4], br[4];
#pragma unroll
                for (int mt = 0; mt < 3; mt++)
                    LDMX4(ar[mt][0], ar[mt][1], ar[mt][2], ar[mt][3],
                          aB + (uint32_t)mt * (16 * SB_LD) + ko);
                LDMX4(br[0], br[1], br[2], br[3], bB + ko);
#pragma unroll
                for (int mt = 0; mt < 3; mt++)
#pragma unroll
                    for (int ns = 0; ns < 2; ns++)
                        MMA16816(av[mt][ns], ar[mt][0], ar[mt][1], ar[mt][2], ar[mt][3],
                                 br[ns * 2], br[ns * 2 + 1]);
            }
        }

        float* bo = g_bo + (((size_t)b * HH + h) * TT_) * DD;
        const int r0 = (lane >> 2);
        const int cc = 2 * (lane & 3);
#pragma unroll
        for (int mt = 0; mt < 3; mt++) {
            int rows[2] = { mb2 + mt * 16 + r0, mb2 + mt * 16 + r0 + 8 };
#pragma unroll
            for (int ns = 0; ns < 2; ns++) {
                int d = nb2 + ns * 8 + cc;
#pragma unroll
                for (int half = 0; half < 2; half++) {
                    int t = rows[half];
                    if (t >= TT_) continue;
                    *(float2*)&bo[(size_t)t * DD + d] =
                        make_float2(av[mt][ns][half * 2], av[mt][ns][half * 2 + 1]);
                }
            }
        }
    }
}

// ---------------------------------------------------------------------------
__device__ __forceinline__ float qgelu4(float s) {
    float u = s + 4.f;
    return u / (1.f + __expf(-1.702f * u)) - 4.f;
}

__global__ void __launch_bounds__(128) reduce_gelu_kernel() {
    int idx = blockIdx.x * 128 + threadIdx.x;
    int m  = idx >> 5, kq = idx & 31;
    int bb = m / TT_, t = m - bb * TT_;
    const float4* base = (const float4*)g_bo + ((size_t)(bb * HH) * TT_ + t) * 32 + kq;
    float s0 = 0.f, s1 = 0.f, s2 = 0.f, s3 = 0.f;
#pragma unroll
    for (int hh = 0; hh < HH; hh++) {
        float4 v = base[(size_t)hh * TT_ * 32];
        s0 += v.x; s1 += v.y; s2 += v.z; s3 += v.w;
    }
    float4 g;
    g.x = qgelu4(s0); g.y = qgelu4(s1); g.z = qgelu4(s2); g.w = qgelu4(s3);
    ((float4*)g_G)[(size_t)m * 32 + kq] = g;
}

__global__ void __launch_bounds__(256) fanout_kernel(const float* __restrict__ x,
                                                     const float* __restrict__ Wf,
                                                     const float* __restrict__ bf,
                                                     float* __restrict__ out) {
    extern __shared__ float sm[];
    float* Ws = sm;                 // [128][64]
    float* Gs = sm + 128 * 64;      // [128][17]
    const int LDG_ = 17;
    const int mtile = blockIdx.x >> 1;
    const int half  = blockIdx.x & 1;
    const int m0 = mtile * 16;
    const int nbase = half * 64;
    const int tid = threadIdx.x;
    {
        int n  = tid & 63, k4 = tid >> 6;
        const float* wr = Wf + (size_t)(nbase + n) * DD;
#pragma unroll
        for (int p = 0; p < 8; p++) {
            int kq = p * 4 + k4;
            float4 w = *(const float4*)(wr + kq * 4);
            Ws[(kq*4+0)*64 + n] = w.x;  Ws[(kq*4+1)*64 + n] = w.y;
            Ws[(kq*4+2)*64 + n] = w.z;  Ws[(kq*4+3)*64 + n] = w.w;
        }
    }
    {
#pragma unroll
        for (int p = 0; p < 2; p++) {
            int i  = p * 256 + tid;
            int ml = i >> 5, kq = i & 31;
            float4 g = ((const float4*)g_G)[(size_t)(m0 + ml) * 32 + kq];
            Gs[(kq*4+0)*LDG_ + ml] = g.x;  Gs[(kq*4+1)*LDG_ + ml] = g.y;
            Gs[(kq*4+2)*LDG_ + ml] = g.z;  Gs[(kq*4+3)*LDG_ + ml] = g.w;
        }
    }
    __syncthreads();
    const int m_ = tid >> 4;
    const int n0 = (tid & 15) * 4;
    float a0 = 0.f, a1 = 0.f, a2 = 0.f, a3 = 0.f;
#pragma unroll 8
    for (int k = 0; k < 128; k++) {
        float g = Gs[k * LDG_ + m_];
        float4 w = *(const float4*)&Ws[k * 64 + n0];
        a0 += g * w.x; a1 += g * w.y; a2 += g * w.z; a3 += g * w.w;
    }
    int m = m0 + m_, ng = nbase + n0;
    float4 xv = *(const float4*)&x[(size_t)m * DD + ng];
    float4 bv = *(const float4*)&bf[ng];
    *(float4*)&out[(size_t)m * DD + ng] =
        make_float4(xv.x + a0 + bv.x, xv.y + a1 + bv.y, xv.z + a2 + bv.z, xv.w + a3 + bv.w);
}

// ---------------------------------------------------------------------------
extern "C" void kernel_launch(void* const* d_in, const int* in_sizes, int n_in,
                              void* d_out, int out_size) {
    const float* x        = (const float*)d_in[0];
    const float* msk      = (const float*)d_in[1];
    const float* wqkv_w   = (const float*)d_in[2];
    const float* wqkv_b   = (const float*)d_in[3];
    const float* wk_w     = (const float*)d_in[4];
    const float* fanout_w = (const float*)d_in[5];
    const float* fanout_b = (const float*)d_in[6];
    const float* head_en  = (const float*)d_in[7];

    float* out = (float*)d_out;
    float* ap_out = out + (size_t)BT * DD;

    const int smemA = SMEM_FLOATS * 4;                   // 219360
    const int smemF = (128*64 + 128*17) * 4 + 16;

    cudaFuncSetAttribute(attn_mma,      cudaFuncAttributeMaxDynamicSharedMemorySize, smemA);
    cudaFuncSetAttribute(fanout_kernel, cudaFuncAttributeMaxDynamicSharedMemorySize, smemF);

    attn_mma<<<BB * HH, NT_, smemA>>>(x, wqkv_w, wqkv_b, wk_w, msk, head_en, ap_out);

    reduce_gelu_kernel<<<324, 128>>>();

    fanout_kernel<<<162, 256, smemF>>>(x, fanout_w, fanout_b, out);
}

// round 16
// speedup vs baseline: 1.0452x; 1.0452x over previous
#include <cuda_runtime.h>
#include <cuda_bf16.h>
#include <math.h>
#include <stdint.h>

#define BB 16
#define TT_ 81
#define DD 128
#define HH 8
#define BT (BB*TT_)       // 1296

__device__ float g_G[BT*DD];     // head-reduced accumulator (pre-zeroed per launch)

// ---------------- packed fp32x2 helpers ----------------
static __device__ __forceinline__ unsigned long long add2(unsigned long long a,
                                                          unsigned long long b) {
    unsigned long long r;
    asm("add.rn.f32x2 %0, %1, %2;" : "=l"(r) : "l"(a), "l"(b));
    return r;
}
static __device__ __forceinline__ float2 unpack2(unsigned long long v) {
    float2 f;
    asm("mov.b64 {%0, %1}, %2;" : "=f"(f.x), "=f"(f.y) : "l"(v));
    return f;
}
#define ABS2MASK 0x7FFFFFFF7FFFFFFFULL

static __device__ __forceinline__ uint32_t smem_to_u32(const void* p) {
    uint32_t a;
    asm("{ .reg .u64 t; cvta.to.shared.u64 t, %1; cvt.u32.u64 %0, t; }" : "=r"(a) : "l"(p));
    return a;
}
#define LDMX4(r0, r1, r2, r3, addr) \
    asm volatile("ldmatrix.sync.aligned.m8n8.x4.shared.b16 {%0,%1,%2,%3}, [%4];" \
        : "=r"(r0), "=r"(r1), "=r"(r2), "=r"(r3) : "r"(addr))
#define MMA16816(c, a0, a1, a2, a3, b0, b1) \
    asm volatile("mma.sync.aligned.m16n8k16.row.col.f32.bf16.bf16.f32 " \
        "{%0,%1,%2,%3}, {%4,%5,%6,%7}, {%8,%9}, {%0,%1,%2,%3};" \
        : "+f"((c)[0]), "+f"((c)[1]), "+f"((c)[2]), "+f"((c)[3]) \
        : "r"(a0), "r"(a1), "r"(a2), "r"(a3), "r"(b0), "r"(b1))

// split 8 floats -> bf16-hi uint4 + bf16-lo uint4
static __device__ __forceinline__ void split8(float4 a, float4 b, uint4& hi, uint4& lo) {
    float va[8] = {a.x, a.y, a.z, a.w, b.x, b.y, b.z, b.w};
    unsigned short h[8], l[8];
#pragma unroll
    for (int i = 0; i < 8; i++) {
        __nv_bfloat16 bh = __float2bfloat16(va[i]);
        h[i] = __bfloat16_as_ushort(bh);
        l[i] = __bfloat16_as_ushort(__float2bfloat16(va[i] - __bfloat162float(bh)));
    }
    hi = make_uint4((uint32_t)h[0]|((uint32_t)h[1]<<16), (uint32_t)h[2]|((uint32_t)h[3]<<16),
                    (uint32_t)h[4]|((uint32_t)h[5]<<16), (uint32_t)h[6]|((uint32_t)h[7]<<16));
    lo = make_uint4((uint32_t)l[0]|((uint32_t)l[1]<<16), (uint32_t)l[2]|((uint32_t)l[3]<<16),
                    (uint32_t)l[4]|((uint32_t)l[5]<<16), (uint32_t)l[6]|((uint32_t)l[7]<<16));
}
// cvt-only: 8 floats -> bf16-hi uint4
static __device__ __forceinline__ uint4 cvt8(float4 a, float4 b) {
    float va[8] = {a.x, a.y, a.z, a.w, b.x, b.y, b.z, b.w};
    unsigned short h[8];
#pragma unroll
    for (int i = 0; i < 8; i++) h[i] = __bfloat16_as_ushort(__float2bfloat16(va[i]));
    return make_uint4((uint32_t)h[0]|((uint32_t)h[1]<<16), (uint32_t)h[2]|((uint32_t)h[3]<<16),
                      (uint32_t)h[4]|((uint32_t)h[5]<<16), (uint32_t)h[6]|((uint32_t)h[7]<<16));
}

// ---- smem layout (identical to R14) ----
#define AHI_B   0
#define ALO_B   26112
#define WB_B    52224
#define SBHI_B  0
#define SBLO_B  19968
#define VTHI_B  52224
#define VTLO_B  78848
#define KT_F    30464
#define LDS_S   84
#define S_F     41216
#define MSK_F   48020
#define BIAS_F  54584
#define SMEM_FLOATS (BIAS_F + 256)   // 54840 fl = 219360 B
#define QV_LD   132
#define SB_LD   208

__global__ void __launch_bounds__(512, 1)
attn_mma(const float* __restrict__ x,
         const float* __restrict__ wqkv_w,
         const float* __restrict__ wqkv_b,
         const float* __restrict__ wk_w,
         const float* __restrict__ msk,
         const float* __restrict__ head_en,
         float* __restrict__ ap_out) {
    extern __shared__ float sm[];
    char* smb = (char*)sm;
    const uint32_t sb = smem_to_u32(sm);
    float* Qs  = sm;                 // stride 132, overlays A after GEMM
    float* KT  = sm + KT_F;
    float* S   = sm + S_F;
    float* Msk = sm + MSK_F;
    float* BiasS = sm + BIAS_F;

    const int b = blockIdx.x >> 3;
    const int h = blockIdx.x & 7;
    const int tid = threadIdx.x;
    const int wid = tid >> 5;
    const int lane = tid & 31;

    const float* xb = x + (size_t)b * TT_ * DD;
    const float* Wg = wqkv_w + ((size_t)h * 2 * DD) * DD;   // 256 x 128

    // ---------------- S1: stage A hi/lo, W hi, bias, KT, Msk ----------------
    for (int idx = tid; idx < 96 * 16; idx += 512) {        // A: (t, k8)
        int t = idx >> 4, k0 = (idx & 15) << 3;
        uint4 hi = make_uint4(0, 0, 0, 0), lo = make_uint4(0, 0, 0, 0);
        if (t < TT_) {
            float4 va = *(const float4*)(xb + t * DD + k0);
            float4 vb = *(const float4*)(xb + t * DD + k0 + 4);
            split8(va, vb, hi, lo);
        }
        uint32_t off = (uint32_t)t * 272 + (uint32_t)k0 * 2;
        *(uint4*)(smb + AHI_B + off) = hi;
        *(uint4*)(smb + ALO_B + off) = lo;
    }
    for (int idx = tid; idx < 256 * 16; idx += 512) {       // W hi only: (n, k8)
        int n = idx >> 4, k0 = (idx & 15) << 3;
        float4 va = *(const float4*)(Wg + (size_t)n * DD + k0);
        float4 vb = *(const float4*)(Wg + (size_t)n * DD + k0 + 4);
        *(uint4*)(smb + WB_B + (uint32_t)n * 272 + (uint32_t)k0 * 2) = cvt8(va, vb);
    }
    if (tid < 256) BiasS[tid] = wqkv_b[h * 256 + tid];
    {   // KT (negated k), Msk
        const float4* x4  = (const float4*)xb;
        const float4* wk4 = (const float4*)(wk_w + h * DD);
        for (int i = tid; i < 32 * TT_; i += 512) {
            int dq = i / TT_, t = i - dq * TT_;
            float4 xv = x4[t * 32 + dq];
            float4 wv = wk4[dq];
            int dp = dq * 2;
            *(float2*)&KT[(dp    ) * 168 + t * 2] = make_float2(-(xv.x*wv.x), -(xv.y*wv.y));
            *(float2*)&KT[(dp + 1) * 168 + t * 2] = make_float2(-(xv.z*wv.z), -(xv.w*wv.w));
        }
        for (int i = tid; i < 192; i += 512) {
            int dp = i / 3, s = 81 + (i % 3);
            *(float2*)&KT[dp * 168 + s * 2] = make_float2(0.f, 0.f);
        }
        const float* mg = msk + (size_t)h * TT_ * TT_;
        for (int i = tid; i < TT_ * TT_; i += 512) Msk[i] = mg[i];
    }
    __syncthreads();

    // ---------------- QKV GEMM: 16 warps x (3 m16 x 4 n8), 2 passes ----------------
    const int mgrp = wid >> 3, ngrp = wid & 7;
    const int mb = mgrp * 48, nb = ngrp * 32;
    const int j = lane >> 3, lr = lane & 7;
    const uint32_t aOff = (uint32_t)(mb + ((j & 1) << 3) + lr) * 272 + ((uint32_t)(j >> 1) << 4);
    const uint32_t bOff = (uint32_t)(nb + ((j >> 1) << 3) + lr) * 272 + ((uint32_t)(j & 1) << 4);
    const uint32_t aHi = sb + AHI_B + aOff;
    const uint32_t aLo = sb + ALO_B + aOff;
    const uint32_t bBs = sb + WB_B + bOff;

    {
        float acc[3][4][4];
#pragma unroll
        for (int m = 0; m < 3; m++)
#pragma unroll
            for (int n = 0; n < 4; n++)
#pragma unroll
                for (int q = 0; q < 4; q++) acc[m][n][q] = 0.f;

#pragma unroll
        for (int pass = 0; pass < 2; pass++) {
            const uint32_t aB = (pass == 1) ? aLo : aHi;
#pragma unroll
            for (int ks = 0; ks < 8; ks++) {
                const uint32_t ko = (uint32_t)ks * 32;
                uint32_t ar[3][4], br[2][4];
#pragma unroll
                for (int mt = 0; mt < 3; mt++)
                    LDMX4(ar[mt][0], ar[mt][1], ar[mt][2], ar[mt][3],
                          aB + (uint32_t)mt * (16 * 272) + ko);
#pragma unroll
                for (int hf = 0; hf < 2; hf++)
                    LDMX4(br[hf][0], br[hf][1], br[hf][2], br[hf][3],
                          bBs + (uint32_t)hf * (16 * 272) + ko);
#pragma unroll
                for (int mt = 0; mt < 3; mt++)
#pragma unroll
                    for (int ns = 0; ns < 4; ns++) {
                        const int hf = ns >> 1, pr = (ns & 1) * 2;
                        MMA16816(acc[mt][ns], ar[mt][0], ar[mt][1], ar[mt][2], ar[mt][3],
                                 br[hf][pr], br[hf][pr + 1]);
                    }
            }
        }
        __syncthreads();    // all ldmatrix reads done before overlays

        // epilogue: +bias; n<128 -> Qs fp32; n>=128 -> VThi/VTlo bf16 [d][s]
        const float he = head_en[h];
        const int r0 = (lane >> 2);
        const int cc = 2 * (lane & 3);
#pragma unroll
        for (int mt = 0; mt < 3; mt++) {
            int rows[2] = { mb + mt * 16 + r0, mb + mt * 16 + r0 + 8 };
#pragma unroll
            for (int ns = 0; ns < 4; ns++) {
                int n = nb + ns * 8 + cc;
                float b0 = BiasS[n], b1 = BiasS[n + 1];
#pragma unroll
                for (int half = 0; half < 2; half++) {
                    int t = rows[half];
                    if (t >= TT_) continue;
                    float v0 = acc[mt][ns][half * 2]     + b0;
                    float v1 = acc[mt][ns][half * 2 + 1] + b1;
                    if (n < 128) {
                        *(float2*)&Qs[t * QV_LD + n] = make_float2(v0, v1);
                    } else {
                        int col = n - 128;
                        float w0 = v0 * he, w1 = v1 * he;
                        __nv_bfloat16 h0 = __float2bfloat16(w0);
                        __nv_bfloat16 h1 = __float2bfloat16(w1);
                        *(__nv_bfloat16*)(smb + VTHI_B + (uint32_t)col * SB_LD + t * 2) = h0;
                        *(__nv_bfloat16*)(smb + VTHI_B + (uint32_t)(col + 1) * SB_LD + t * 2) = h1;
                        *(__nv_bfloat16*)(smb + VTLO_B + (uint32_t)col * SB_LD + t * 2) =
                            __float2bfloat16(w0 - __bfloat162float(h0));
                        *(__nv_bfloat16*)(smb + VTLO_B + (uint32_t)(col + 1) * SB_LD + t * 2) =
                            __float2bfloat16(w1 - __bfloat162float(h1));
                    }
                }
            }
        }
        // zero VT pad cols s=81..95 for all 128 d, both mats
        for (int i = tid; i < 1920; i += 512) {
            int d = i / 15, s = 81 + (i % 15);
            *(__nv_bfloat16*)(smb + VTHI_B + (uint32_t)d * SB_LD + s * 2) = __float2bfloat16(0.f);
            *(__nv_bfloat16*)(smb + VTLO_B + (uint32_t)d * SB_LD + s * 2) = __float2bfloat16(0.f);
        }
    }
    __syncthreads();

    // ---------------- P2: scores (fp32, f32x2+AND) ----------------
    const float scale = 0.08838834764831843f;
    if (tid < 441) {
        const int t0s = (tid / 21) * 4;
        const int s0 = (tid % 21) * 4;
        int ti[4];
#pragma unroll
        for (int i = 0; i < 4; i++) ti[i] = min(t0s + i, TT_ - 1);
        unsigned long long sacc[4][4];
#pragma unroll
        for (int i = 0; i < 4; i++)
#pragma unroll
            for (int q = 0; q < 4; q++) sacc[i][q] = 0ULL;
#pragma unroll 1
        for (int d = 0; d < DD; d += 4) {
            const int dp = d >> 1;
            ulonglong2 q[4];
#pragma unroll
            for (int i = 0; i < 4; i++)
                q[i] = *(const ulonglong2*)&Qs[ti[i] * QV_LD + d];
            ulonglong2 ka = *(const ulonglong2*)&KT[(dp    ) * 168 + s0 * 2];
            ulonglong2 kb = *(const ulonglong2*)&KT[(dp    ) * 168 + s0 * 2 + 4];
            ulonglong2 kc = *(const ulonglong2*)&KT[(dp + 1) * 168 + s0 * 2];
            ulonglong2 kd = *(const ulonglong2*)&KT[(dp + 1) * 168 + s0 * 2 + 4];
#pragma unroll
            for (int i = 0; i < 4; i++) {
                unsigned long long u;
                u = add2(q[i].x, ka.x) & ABS2MASK;  sacc[i][0] = add2(sacc[i][0], u);
                u = add2(q[i].y, kc.x) & ABS2MASK;  sacc[i][0] = add2(sacc[i][0], u);
                u = add2(q[i].x, ka.y) & ABS2MASK;  sacc[i][1] = add2(sacc[i][1], u);
                u = add2(q[i].y, kc.y) & ABS2MASK;  sacc[i][1] = add2(sacc[i][1], u);
                u = add2(q[i].x, kb.x) & ABS2MASK;  sacc[i][2] = add2(sacc[i][2], u);
                u = add2(q[i].y, kd.x) & ABS2MASK;  sacc[i][2] = add2(sacc[i][2], u);
                u = add2(q[i].x, kb.y) & ABS2MASK;  sacc[i][3] = add2(sacc[i][3], u);
                u = add2(q[i].y, kd.y) & ABS2MASK;  sacc[i][3] = add2(sacc[i][3], u);
            }
        }
#pragma unroll
        for (int i = 0; i < 4; i++) {
            if (t0s + i >= TT_) continue;
#pragma unroll
            for (int q = 0; q < 4; q++) {
                if (s0 + q >= TT_) continue;
                float2 f = unpack2(sacc[i][q]);
                S[(s0 + q) * LDS_S + (t0s + i)] = -(f.x + f.y) * scale;
            }
        }
    }
    __syncthreads();

    // ---------------- P3: softmax; writes Sbhi/Sblo [t][s] bf16 + ap ----------------
    if (tid < 352) {
        const int t  = tid >> 2;
        const int l4 = tid & 3;
        const bool valid = (t < TT_);
        const int sBeg = l4 * 21;
        const int sEnd = valid ? min(sBeg + 21, TT_) : sBeg;
        float mx = -1e30f;
        for (int s = sBeg; s < sEnd; s++) mx = fmaxf(mx, S[s * LDS_S + t]);
        mx = fmaxf(mx, __shfl_xor_sync(0xFFFFFFFFu, mx, 1));
        mx = fmaxf(mx, __shfl_xor_sync(0xFFFFFFFFu, mx, 2));
        float sum = 0.f;
        for (int s = sBeg; s < sEnd; s++) {
            float e = __expf(S[s * LDS_S + t] - mx);
            sum += e;
            S[s * LDS_S + t] = e;
        }
        sum += __shfl_xor_sync(0xFFFFFFFFu, sum, 1);
        sum += __shfl_xor_sync(0xFFFFFFFFu, sum, 2);
        float inv = 1.f / sum;
        for (int s = sBeg; s < sEnd; s++) {
            float mval = Msk[t * TT_ + s];
            float a = S[s * LDS_S + t] * inv * mval;
            __nv_bfloat16 hv = __float2bfloat16(a);
            *(__nv_bfloat16*)(smb + SBHI_B + (uint32_t)t * SB_LD + s * 2) = hv;
            *(__nv_bfloat16*)(smb + SBLO_B + (uint32_t)t * SB_LD + s * 2) =
                __float2bfloat16(a - __bfloat162float(hv));
            if (b == 0)
                ap_out[((size_t)t * TT_ + s) * HH + h] = a - 1.f + mval;
        }
    } else {
        // zero Sb pads: t rows 81..95 full; s cols 81..95 for t<=80 (both mats)
        for (int i = tid - 352; i < 780; i += 160) {
            int row = 81 + i / 52, w = i % 52;
            *(uint32_t*)(smb + SBHI_B + (uint32_t)row * SB_LD + w * 4) = 0u;
            *(uint32_t*)(smb + SBLO_B + (uint32_t)row * SB_LD + w * 4) = 0u;
        }
        for (int i = tid - 352; i < 1215; i += 160) {
            int t = i / 15, s = 81 + (i % 15);
            *(__nv_bfloat16*)(smb + SBHI_B + (uint32_t)t * SB_LD + s * 2) = __float2bfloat16(0.f);
            *(__nv_bfloat16*)(smb + SBLO_B + (uint32_t)t * SB_LD + s * 2) = __float2bfloat16(0.f);
        }
    }
    __syncthreads();

    // ---------------- P4: AV via HMMA, 3 passes -> RED.ADD g_G ----------------
    {
        const int mb2 = (wid >> 3) * 48;        // 2 m-groups x 3 m16
        const int nb2 = (wid & 7) * 16;         // 8 n-groups x 2 n8
        const uint32_t aOffAV = (uint32_t)(mb2 + ((j & 1) << 3) + lr) * SB_LD + ((uint32_t)(j >> 1) << 4);
        const uint32_t bOffAV = (uint32_t)(nb2 + ((j >> 1) << 3) + lr) * SB_LD + ((uint32_t)(j & 1) << 4);

        float av[3][2][4];
#pragma unroll
        for (int m = 0; m < 3; m++)
#pragma unroll
            for (int n = 0; n < 2; n++)
#pragma unroll
                for (int q = 0; q < 4; q++) av[m][n][q] = 0.f;

#pragma unroll
        for (int pass = 0; pass < 3; pass++) {
            const uint32_t aB = sb + ((pass == 1) ? SBLO_B : SBHI_B) + aOffAV;
            const uint32_t bB = sb + ((pass == 2) ? VTLO_B : VTHI_B) + bOffAV;
#pragma unroll
            for (int ks = 0; ks < 6; ks++) {
                const uint32_t ko = (uint32_t)ks * 32;
                uint32_t ar[3][4], br[4];
#pragma unroll
                for (int mt = 0; mt < 3; mt++)
                    LDMX4(ar[mt][0], ar[mt][1], ar[mt][2], ar[mt][3],
                          aB + (uint32_t)mt * (16 * SB_LD) + ko);
                LDMX4(br[0], br[1], br[2], br[3], bB + ko);
#pragma unroll
                for (int mt = 0; mt < 3; mt++)
#pragma unroll
                    for (int ns = 0; ns < 2; ns++)
                        MMA16816(av[mt][ns], ar[mt][0], ar[mt][1], ar[mt][2], ar[mt][3],
                                 br[ns * 2], br[ns * 2 + 1]);
            }
        }

        float* gG = g_G + (size_t)b * TT_ * DD;
        const int r0 = (lane >> 2);
        const int cc = 2 * (lane & 3);
#pragma unroll
        for (int mt = 0; mt < 3; mt++) {
            int rows[2] = { mb2 + mt * 16 + r0, mb2 + mt * 16 + r0 + 8 };
#pragma unroll
            for (int ns = 0; ns < 2; ns++) {
                int d = nb2 + ns * 8 + cc;
#pragma unroll
                for (int half = 0; half < 2; half++) {
                    int t = rows[half];
                    if (t >= TT_) continue;
                    atomicAdd(&gG[(size_t)t * DD + d],     av[mt][ns][half * 2]);
                    atomicAdd(&gG[(size_t)t * DD + d + 1], av[mt][ns][half * 2 + 1]);
                }
            }
        }
    }
}

// ---------------------------------------------------------------------------
__device__ __forceinline__ float qgelu4(float s) {
    float u = s + 4.f;
    return u / (1.f + __expf(-1.702f * u)) - 4.f;
}

// out = x + qgelu(g_G)@Wf^T + bf.  162 blocks (16m x 64n), 256 threads.
__global__ void __launch_bounds__(256) fanout_kernel(const float* __restrict__ x,
                                                     const float* __restrict__ Wf,
                                                     const float* __restrict__ bf,
                                                     float* __restrict__ out) {
    extern __shared__ float sm[];
    float* Ws = sm;                 // [128][64]
    float* Gs = sm + 128 * 64;      // [128][17]
    const int LDG_ = 17;
    const int mtile = blockIdx.x >> 1;
    const int half  = blockIdx.x & 1;
    const int m0 = mtile * 16;
    const int nbase = half * 64;
    const int tid = threadIdx.x;
    {
        int n  = tid & 63, k4 = tid >> 6;
        const float* wr = Wf + (size_t)(nbase + n) * DD;
#pragma unroll
        for (int p = 0; p < 8; p++) {
            int kq = p * 4 + k4;
            float4 w = *(const float4*)(wr + kq * 4);
            Ws[(kq*4+0)*64 + n] = w.x;  Ws[(kq*4+1)*64 + n] = w.y;
            Ws[(kq*4+2)*64 + n] = w.z;  Ws[(kq*4+3)*64 + n] = w.w;
        }
    }
    {
#pragma unroll
        for (int p = 0; p < 2; p++) {
            int i  = p * 256 + tid;
            int ml = i >> 5, kq = i & 31;
            float4 g = ((const float4*)g_G)[(size_t)(m0 + ml) * 32 + kq];
            Gs[(kq*4+0)*LDG_ + ml] = qgelu4(g.x);
            Gs[(kq*4+1)*LDG_ + ml] = qgelu4(g.y);
            Gs[(kq*4+2)*LDG_ + ml] = qgelu4(g.z);
            Gs[(kq*4+3)*LDG_ + ml] = qgelu4(g.w);
        }
    }
    __syncthreads();
    const int m_ = tid >> 4;
    const int n0 = (tid & 15) * 4;
    float a0 = 0.f, a1 = 0.f, a2 = 0.f, a3 = 0.f;
#pragma unroll 8
    for (int k = 0; k < 128; k++) {
        float g = Gs[k * LDG_ + m_];
        float4 w = *(const float4*)&Ws[k * 64 + n0];
        a0 += g * w.x; a1 += g * w.y; a2 += g * w.z; a3 += g * w.w;
    }
    int m = m0 + m_, ng = nbase + n0;
    float4 xv = *(const float4*)&x[(size_t)m * DD + ng];
    float4 bv = *(const float4*)&bf[ng];
    *(float4*)&out[(size_t)m * DD + ng] =
        make_float4(xv.x + a0 + bv.x, xv.y + a1 + bv.y, xv.z + a2 + bv.z, xv.w + a3 + bv.w);
}

// ---------------------------------------------------------------------------
extern "C" void kernel_launch(void* const* d_in, const int* in_sizes, int n_in,
                              void* d_out, int out_size) {
    const float* x        = (const float*)d_in[0];
    const float* msk      = (const float*)d_in[1];
    const float* wqkv_w   = (const float*)d_in[2];
    const float* wqkv_b   = (const float*)d_in[3];
    const float* wk_w     = (const float*)d_in[4];
    const float* fanout_w = (const float*)d_in[5];
    const float* fanout_b = (const float*)d_in[6];
    const float* head_en  = (const float*)d_in[7];

    float* out = (float*)d_out;
    float* ap_out = out + (size_t)BT * DD;

    const int smemA = SMEM_FLOATS * 4;                   // 219360
    const int smemF = (128*64 + 128*17) * 4 + 16;

    cudaFuncSetAttribute(attn_mma,      cudaFuncAttributeMaxDynamicSharedMemorySize, smemA);
    cudaFuncSetAttribute(fanout_kernel, cudaFuncAttributeMaxDynamicSharedMemorySize, smemF);

    // zero the head-reduction accumulator (graph-capturable async memset)
    void* gG_ptr = nullptr;
    cudaGetSymbolAddress(&gG_ptr, g_G);
    cudaMemsetAsync(gG_ptr, 0, (size_t)BT * DD * sizeof(float), 0);

    attn_mma<<<BB * HH, 512, smemA>>>(x, wqkv_w, wqkv_b, wk_w, msk, head_en, ap_out);

    fanout_kernel<<<162, 256, smemF>>>(x, fanout_w, fanout_b, out);
}